// round 1
// baseline (speedup 1.0000x reference)
#include <cuda_runtime.h>
#include <math.h>

// Problem constants
#define B_ 2
#define S_ 2048
#define D_ 1024
#define H_ 16
#define HD_ 64
#define NEGINF (-9000000000000000.0f)

// Scratch (device globals: allocation-free rule)
__device__ float g_Q[B_ * H_ * S_ * HD_];   // [B,H,S,hd]
__device__ float g_K[B_ * H_ * S_ * HD_];
__device__ float g_V[B_ * H_ * S_ * HD_];
__device__ float g_C[B_ * S_ * D_];         // ctx, [B,S,D]

// ---------------------------------------------------------------------------
// Tiled fp32 GEMM: C[M,N] = A[M,K=1024] @ W[N,K=1024]^T + bias
// 64x64 tile, BK=16, 256 threads, 4x4 register blocking.
// MODE 0: A = x, N=3072, scatter into g_Q/g_K/g_V ([B,H,S,hd])
// MODE 1: A = g_C, N=1024, write to out
// ---------------------------------------------------------------------------
template <int MODE>
__global__ __launch_bounds__(256) void gemm64(const float* __restrict__ A,
                                              const float* __restrict__ W,
                                              const float* __restrict__ bias,
                                              float* __restrict__ out) {
    __shared__ float As[16][64];  // [k][m] transposed
    __shared__ float Bs[16][64];  // [k][n] transposed

    const int m0 = blockIdx.y * 64;
    const int n0 = blockIdx.x * 64;
    const int t  = threadIdx.x;
    const int ty = t >> 4;        // 0..15
    const int tx = t & 15;        // 0..15
    const int lr = t >> 2;        // 0..63 (load row)
    const int ls = t & 3;         // 0..3  (load segment)

    const float* Aptr = (MODE == 1 ? g_C : A);
    const float* Ap = Aptr + (size_t)(m0 + lr) * D_ + ls * 4;
    const float* Wp = W + (size_t)(n0 + lr) * D_ + ls * 4;

    float acc[4][4] = {};

    for (int k0 = 0; k0 < D_; k0 += 16) {
        float4 a4 = *(const float4*)(Ap + k0);
        float4 b4 = *(const float4*)(Wp + k0);
        As[ls * 4 + 0][lr] = a4.x;
        As[ls * 4 + 1][lr] = a4.y;
        As[ls * 4 + 2][lr] = a4.z;
        As[ls * 4 + 3][lr] = a4.w;
        Bs[ls * 4 + 0][lr] = b4.x;
        Bs[ls * 4 + 1][lr] = b4.y;
        Bs[ls * 4 + 2][lr] = b4.z;
        Bs[ls * 4 + 3][lr] = b4.w;
        __syncthreads();
#pragma unroll
        for (int k = 0; k < 16; ++k) {
            float4 av = *(const float4*)&As[k][ty * 4];
            float4 bv = *(const float4*)&Bs[k][tx * 4];
            float a[4] = {av.x, av.y, av.z, av.w};
            float b[4] = {bv.x, bv.y, bv.z, bv.w};
#pragma unroll
            for (int i = 0; i < 4; ++i)
#pragma unroll
                for (int j = 0; j < 4; ++j)
                    acc[i][j] += a[i] * b[j];
        }
        __syncthreads();
    }

    if (MODE == 0) {
        // scatter into Q/K/V: n -> (h, part, d): n = h*192 + part*64 + d
#pragma unroll
        for (int i = 0; i < 4; ++i) {
            int m  = m0 + ty * 4 + i;
            int bb = m >> 11;       // / 2048
            int ss = m & 2047;
#pragma unroll
            for (int j = 0; j < 4; ++j) {
                int n = n0 + tx * 4 + j;
                float v = acc[i][j] + __ldg(&bias[n]);
                int h    = n / 192;
                int rem  = n - h * 192;
                int part = rem >> 6;
                int d    = rem & 63;
                size_t dst = (((size_t)(bb * H_ + h)) * S_ + ss) * HD_ + d;
                if (part == 0)      g_Q[dst] = v;
                else if (part == 1) g_K[dst] = v;
                else                g_V[dst] = v;
            }
        }
    } else {
        float4 bv = *(const float4*)&bias[n0 + tx * 4];
#pragma unroll
        for (int i = 0; i < 4; ++i) {
            int m = m0 + ty * 4 + i;
            float4 o4;
            o4.x = acc[i][0] + bv.x;
            o4.y = acc[i][1] + bv.y;
            o4.z = acc[i][2] + bv.z;
            o4.w = acc[i][3] + bv.w;
            *(float4*)&out[(size_t)m * D_ + n0 + tx * 4] = o4;
        }
    }
}

// ---------------------------------------------------------------------------
// Flash attention, fp32. grid = (S/64 q-tiles, B*H). 256 threads.
// Tiles: Qs[d][r], Ks[d][c] (transposed, conflict-free stores), Vs[kk][d],
// Ss[r][c]. Online softmax with shuffle reductions over the 16 tx lanes.
// ---------------------------------------------------------------------------
__global__ __launch_bounds__(256) void attn_kernel(const int* __restrict__ mask) {
    extern __shared__ float sh[];
    float* Qs = sh;            // 64*64  [d][r]
    float* Ks = sh + 4096;     // 64*64  [d][c]
    float* Vs = sh + 8192;     // 64*64  [kk][d]
    float* Ss = sh + 12288;    // 64*64  [r][c]
    __shared__ float sm_m[64];
    __shared__ float sm_l[64];

    const int bh = blockIdx.y;          // b*H + h
    const int q0 = blockIdx.x * 64;
    const int t  = threadIdx.x;
    const int ty = t >> 4;
    const int tx = t & 15;

    const size_t base = (size_t)bh * (S_ * HD_);
    const float* Qg = g_Q + base;
    const float* Kg = g_K + base;
    const float* Vg = g_V + base;

    // Load Q tile transposed: Qs[d][r]. Conflict-free store mapping.
#pragma unroll
    for (int i = 0; i < 4; ++i) {
        int idx = t + i * 256;          // 0..1023
        int row = idx & 63;
        int sg  = idx >> 6;             // 0..15
        float4 q4 = *(const float4*)(Qg + (size_t)(q0 + row) * HD_ + sg * 4);
        Qs[(sg * 4 + 0) * 64 + row] = q4.x;
        Qs[(sg * 4 + 1) * 64 + row] = q4.y;
        Qs[(sg * 4 + 2) * 64 + row] = q4.z;
        Qs[(sg * 4 + 3) * 64 + row] = q4.w;
    }
    if (t < 64) { sm_m[t] = -INFINITY; sm_l[t] = 0.0f; }

    float o[4][4] = {};
    __syncthreads();

    for (int j = 0; j < 32; ++j) {
        // Load K (transposed) and V (natural)
#pragma unroll
        for (int i = 0; i < 4; ++i) {
            int idx = t + i * 256;
            int row = idx & 63;
            int sg  = idx >> 6;
            float4 k4 = *(const float4*)(Kg + (size_t)(j * 64 + row) * HD_ + sg * 4);
            Ks[(sg * 4 + 0) * 64 + row] = k4.x;
            Ks[(sg * 4 + 1) * 64 + row] = k4.y;
            Ks[(sg * 4 + 2) * 64 + row] = k4.z;
            Ks[(sg * 4 + 3) * 64 + row] = k4.w;
            int row2 = idx >> 4;
            int sg2  = idx & 15;
            float4 v4 = *(const float4*)(Vg + (size_t)(j * 64 + row2) * HD_ + sg2 * 4);
            *(float4*)&Vs[row2 * 64 + sg2 * 4] = v4;
        }
        __syncthreads();

        // S = Q @ K^T  (inner dim d = 64)
        float s[4][4] = {};
#pragma unroll 16
        for (int d = 0; d < 64; ++d) {
            float4 qv = *(const float4*)&Qs[d * 64 + ty * 4];
            float4 kv = *(const float4*)&Ks[d * 64 + tx * 4];
            float qa[4] = {qv.x, qv.y, qv.z, qv.w};
            float ka[4] = {kv.x, kv.y, kv.z, kv.w};
#pragma unroll
            for (int i = 0; i < 4; ++i)
#pragma unroll
                for (int jj = 0; jj < 4; ++jj)
                    s[i][jj] += qa[i] * ka[jj];
        }

        // scale + mask
#pragma unroll
        for (int i = 0; i < 4; ++i) {
            int qrow = q0 + ty * 4 + i;
#pragma unroll
            for (int jj = 0; jj < 4; ++jj) {
                int kcol = j * 64 + tx * 4 + jj;
                float v = s[i][jj] * 0.125f;   // 1/sqrt(64)
                if (__ldg(&mask[(size_t)qrow * S_ + kcol]) == 0) v = NEGINF;
                s[i][jj] = v;
            }
        }

        // online softmax: row reductions across the 16 tx lanes (shfl_xor)
        float alpha[4];
#pragma unroll
        for (int i = 0; i < 4; ++i) {
            float mx = fmaxf(fmaxf(s[i][0], s[i][1]), fmaxf(s[i][2], s[i][3]));
#pragma unroll
            for (int w = 1; w < 16; w <<= 1)
                mx = fmaxf(mx, __shfl_xor_sync(0xffffffffu, mx, w));
            int r = ty * 4 + i;
            float mo = sm_m[r];
            float mn = fmaxf(mo, mx);
            alpha[i] = __expf(mo - mn);
            float rs = 0.0f;
#pragma unroll
            for (int jj = 0; jj < 4; ++jj) {
                float p = __expf(s[i][jj] - mn);
                s[i][jj] = p;
                rs += p;
            }
#pragma unroll
            for (int w = 1; w < 16; w <<= 1)
                rs += __shfl_xor_sync(0xffffffffu, rs, w);
            if (tx == 0) {
                sm_l[r] = alpha[i] * sm_l[r] + rs;
                sm_m[r] = mn;
            }
            // store P row chunk; rescale O
            *(float4*)&Ss[r * 64 + tx * 4] =
                make_float4(s[i][0], s[i][1], s[i][2], s[i][3]);
#pragma unroll
            for (int jj = 0; jj < 4; ++jj) o[i][jj] *= alpha[i];
        }
        __syncthreads();

        // O += P @ V
#pragma unroll 8
        for (int kk = 0; kk < 64; ++kk) {
            float4 vv = *(const float4*)&Vs[kk * 64 + tx * 4];
            float va[4] = {vv.x, vv.y, vv.z, vv.w};
#pragma unroll
            for (int i = 0; i < 4; ++i) {
                float p = Ss[(ty * 4 + i) * 64 + kk];
#pragma unroll
                for (int jj = 0; jj < 4; ++jj)
                    o[i][jj] += p * va[jj];
            }
        }
        __syncthreads();
    }

    // epilogue: normalize, write ctx [B,S,D] with D index = h*64 + d
    const int bb = bh >> 4;
    const int h  = bh & 15;
#pragma unroll
    for (int i = 0; i < 4; ++i) {
        int r = ty * 4 + i;
        float inv = 1.0f / sm_l[r];
        float4 o4;
        o4.x = o[i][0] * inv;
        o4.y = o[i][1] * inv;
        o4.z = o[i][2] * inv;
        o4.w = o[i][3] * inv;
        size_t dst = ((size_t)bb * S_ + q0 + r) * D_ + h * 64 + tx * 4;
        *(float4*)&g_C[dst] = o4;
    }
}

// ---------------------------------------------------------------------------
extern "C" void kernel_launch(void* const* d_in, const int* in_sizes, int n_in,
                              void* d_out, int out_size) {
    const float* x      = (const float*)d_in[0];
    const int*   mask   = (const int*)d_in[1];
    const float* w_qkv  = (const float*)d_in[2];
    const float* b_qkv  = (const float*)d_in[3];
    const float* w_o    = (const float*)d_in[4];
    const float* b_o    = (const float*)d_in[5];
    float* out = (float*)d_out;

    // 1) QKV projection -> g_Q/g_K/g_V
    gemm64<0><<<dim3(3072 / 64, 4096 / 64), 256>>>(x, w_qkv, b_qkv, nullptr);

    // 2) flash attention -> g_C
    const int attn_smem = 4 * 64 * 64 * (int)sizeof(float);  // 65536
    cudaFuncSetAttribute(attn_kernel, cudaFuncAttributeMaxDynamicSharedMemorySize,
                         attn_smem);
    attn_kernel<<<dim3(S_ / 64, B_ * H_), 256, attn_smem>>>(mask);

    // 3) output projection -> out
    gemm64<1><<<dim3(1024 / 64, 4096 / 64), 256>>>(nullptr, w_o, b_o, out);
}

// round 2
// speedup vs baseline: 3.1218x; 3.1218x over previous
#include <cuda_runtime.h>
#include <math.h>

#define B_ 2
#define S_ 2048
#define D_ 1024
#define H_ 16
#define HD_ 64
#define NEGINF (-9000000000000000.0f)

// Scratch (device globals: allocation-free rule)
__device__ float g_Q[B_ * H_ * S_ * HD_];   // [B,H,S,hd]
__device__ float g_K[B_ * H_ * S_ * HD_];
__device__ float g_V[B_ * H_ * S_ * HD_];
__device__ float g_C[B_ * S_ * D_];         // ctx [B,S,D]

__device__ __forceinline__ unsigned f2tf(float x) {
    unsigned r;
    asm("cvt.rna.tf32.f32 %0, %1;" : "=r"(r) : "f"(x));
    return r;
}

__device__ __forceinline__ void mma_tf32(float c[4], unsigned a0, unsigned a1,
                                         unsigned a2, unsigned a3,
                                         unsigned b0, unsigned b1) {
    asm volatile(
        "mma.sync.aligned.m16n8k8.row.col.f32.tf32.tf32.f32 "
        "{%0,%1,%2,%3}, {%4,%5,%6,%7}, {%8,%9}, {%0,%1,%2,%3};"
        : "+f"(c[0]), "+f"(c[1]), "+f"(c[2]), "+f"(c[3])
        : "r"(a0), "r"(a1), "r"(a2), "r"(a3), "r"(b0), "r"(b1));
}

// ---------------------------------------------------------------------------
// Tensor-core GEMM: C[M,N] = A[M,1024] @ W[N,1024]^T + bias
// Block 128x64, BK=64, 8 warps (4x2), warp tile 32x32 (2 m16 x 4 n8).
// smem pad-stride 68 -> conflict-free fragment loads (bank = 4g+t4).
// MODE 0: A = x, N=3072, scatter into g_Q/g_K/g_V. MODE 1: A = g_C, N=1024.
// ---------------------------------------------------------------------------
template <int MODE>
__global__ __launch_bounds__(256) void gemm_tc(const float* __restrict__ A,
                                               const float* __restrict__ W,
                                               const float* __restrict__ bias,
                                               float* __restrict__ out) {
    extern __shared__ unsigned sh[];
    unsigned* As = sh;              // [128][68]
    unsigned* Bs = sh + 128 * 68;   // [64][68]

    const int m0 = blockIdx.y * 128;
    const int n0 = blockIdx.x * 64;
    const int t = threadIdx.x;
    const int w = t >> 5;
    const int lane = t & 31;
    const int g = lane >> 2;
    const int t4 = lane & 3;
    const int wm = (w >> 1) * 32;   // warp row offset
    const int wn = (w & 1) * 32;    // warp col offset

    const float* Aptr = (MODE == 1 ? g_C : A);

    float acc[2][4][4];
#pragma unroll
    for (int mt = 0; mt < 2; ++mt)
#pragma unroll
        for (int nt = 0; nt < 4; ++nt)
#pragma unroll
            for (int i = 0; i < 4; ++i) acc[mt][nt][i] = 0.0f;

    for (int k0 = 0; k0 < D_; k0 += 64) {
        // stage A tile 128x64 (tf32)
#pragma unroll
        for (int i = 0; i < 8; ++i) {
            int idx = t + i * 256;
            int row = idx >> 4, seg = idx & 15;
            float4 v = *(const float4*)(Aptr + (size_t)(m0 + row) * D_ + k0 + seg * 4);
            unsigned* p = &As[row * 68 + seg * 4];
            p[0] = f2tf(v.x); p[1] = f2tf(v.y); p[2] = f2tf(v.z); p[3] = f2tf(v.w);
        }
        // stage W tile 64x64
#pragma unroll
        for (int i = 0; i < 4; ++i) {
            int idx = t + i * 256;
            int row = idx >> 4, seg = idx & 15;
            float4 v = *(const float4*)(W + (size_t)(n0 + row) * D_ + k0 + seg * 4);
            unsigned* p = &Bs[row * 68 + seg * 4];
            p[0] = f2tf(v.x); p[1] = f2tf(v.y); p[2] = f2tf(v.z); p[3] = f2tf(v.w);
        }
        __syncthreads();

#pragma unroll
        for (int ks = 0; ks < 8; ++ks) {
            unsigned a[2][4];
#pragma unroll
            for (int mt = 0; mt < 2; ++mt) {
                const unsigned* q = &As[(wm + mt * 16) * 68 + ks * 8];
                a[mt][0] = q[g * 68 + t4];
                a[mt][1] = q[(g + 8) * 68 + t4];
                a[mt][2] = q[g * 68 + t4 + 4];
                a[mt][3] = q[(g + 8) * 68 + t4 + 4];
            }
#pragma unroll
            for (int nt = 0; nt < 4; ++nt) {
                unsigned b0 = Bs[(wn + nt * 8 + g) * 68 + ks * 8 + t4];
                unsigned b1 = Bs[(wn + nt * 8 + g) * 68 + ks * 8 + t4 + 4];
                mma_tf32(acc[0][nt], a[0][0], a[0][1], a[0][2], a[0][3], b0, b1);
                mma_tf32(acc[1][nt], a[1][0], a[1][1], a[1][2], a[1][3], b0, b1);
            }
        }
        __syncthreads();
    }

    // epilogue
#pragma unroll
    for (int mt = 0; mt < 2; ++mt) {
#pragma unroll
        for (int nt = 0; nt < 4; ++nt) {
            int ncol = n0 + wn + nt * 8 + 2 * t4;
            float bx = __ldg(&bias[ncol]);
            float by = __ldg(&bias[ncol + 1]);
#pragma unroll
            for (int rr = 0; rr < 2; ++rr) {
                int m = m0 + wm + mt * 16 + g + rr * 8;
                float vx = acc[mt][nt][rr * 2] + bx;
                float vy = acc[mt][nt][rr * 2 + 1] + by;
                if (MODE == 0) {
                    int bb = m >> 11, ss = m & 2047;
                    int h = ncol / 192;
                    int rem = ncol - h * 192;
                    int part = rem >> 6;
                    int d = rem & 63;
                    size_t dst = (((size_t)(bb * H_ + h)) * S_ + ss) * HD_ + d;
                    float* dstp = (part == 0 ? g_Q : (part == 1 ? g_K : g_V));
                    dstp[dst] = vx;
                    dstp[dst + 1] = vy;  // pair never crosses a 64-col part
                } else {
                    *(float2*)&out[(size_t)m * D_ + ncol] = make_float2(vx, vy);
                }
            }
        }
    }
}

// ---------------------------------------------------------------------------
// Flash attention with tf32 mma. grid=(S/128, B*H), 256 threads.
// Each warp owns 16 full q-rows (16x64 S-tile -> softmax stats in registers).
// Qs/Ks stride 68 (bank=4g+t4, conflict-free), Vs stride 72 (bank=8t4+g).
// P is relaid C-frag -> A-frag via 8 shfl per k-tile (no smem round trip).
// ---------------------------------------------------------------------------
__global__ __launch_bounds__(256, 2) void attn_tc(const int* __restrict__ mask) {
    extern __shared__ unsigned sh[];
    unsigned* Qs = sh;                 // [128][68]
    unsigned* Ks = sh + 128 * 68;      // [64][68]
    unsigned* Vs = Ks + 64 * 68;       // [64][72]

    const int bh = blockIdx.y;
    const int q0 = blockIdx.x * 128;
    const int t = threadIdx.x;
    const int w = t >> 5;
    const int lane = t & 31;
    const int g = lane >> 2;
    const int t4 = lane & 3;

    const size_t base = (size_t)bh * (S_ * HD_);
    const float* Qg = g_Q + base;
    const float* Kg = g_K + base;
    const float* Vg = g_V + base;

    // stage Q tile (tf32)
#pragma unroll
    for (int i = 0; i < 8; ++i) {
        int idx = t + i * 256;
        int row = idx >> 4, seg = idx & 15;
        float4 v = *(const float4*)(Qg + (size_t)(q0 + row) * HD_ + seg * 4);
        unsigned* p = &Qs[row * 68 + seg * 4];
        p[0] = f2tf(v.x); p[1] = f2tf(v.y); p[2] = f2tf(v.z); p[3] = f2tf(v.w);
    }

    const int qrow0 = q0 + w * 16 + g;
    const int qrow1 = qrow0 + 8;
    const int* mrow0 = mask + (size_t)qrow0 * S_;
    const int* mrow1 = mask + (size_t)qrow1 * S_;

    float o[8][4];
#pragma unroll
    for (int nt = 0; nt < 8; ++nt)
#pragma unroll
        for (int i = 0; i < 4; ++i) o[nt][i] = 0.0f;
    float m0s = -INFINITY, m1s = -INFINITY, l0 = 0.0f, l1 = 0.0f;

    __syncthreads();

    for (int j = 0; j < 32; ++j) {
        // stage K, V tiles
#pragma unroll
        for (int i = 0; i < 4; ++i) {
            int idx = t + i * 256;
            int row = idx >> 4, seg = idx & 15;
            float4 kv = *(const float4*)(Kg + (size_t)(j * 64 + row) * HD_ + seg * 4);
            unsigned* p = &Ks[row * 68 + seg * 4];
            p[0] = f2tf(kv.x); p[1] = f2tf(kv.y); p[2] = f2tf(kv.z); p[3] = f2tf(kv.w);
            float4 vv = *(const float4*)(Vg + (size_t)(j * 64 + row) * HD_ + seg * 4);
            unsigned* q = &Vs[row * 72 + seg * 4];
            q[0] = f2tf(vv.x); q[1] = f2tf(vv.y); q[2] = f2tf(vv.z); q[3] = f2tf(vv.w);
        }
        __syncthreads();

        // S = Q @ K^T
        float sc[8][4];
#pragma unroll
        for (int nt = 0; nt < 8; ++nt)
#pragma unroll
            for (int i = 0; i < 4; ++i) sc[nt][i] = 0.0f;
#pragma unroll
        for (int ks = 0; ks < 8; ++ks) {
            const unsigned* qb = &Qs[(w * 16) * 68 + ks * 8];
            unsigned a0 = qb[g * 68 + t4];
            unsigned a1 = qb[(g + 8) * 68 + t4];
            unsigned a2 = qb[g * 68 + t4 + 4];
            unsigned a3 = qb[(g + 8) * 68 + t4 + 4];
#pragma unroll
            for (int nt = 0; nt < 8; ++nt) {
                unsigned b0 = Ks[(nt * 8 + g) * 68 + ks * 8 + t4];
                unsigned b1 = Ks[(nt * 8 + g) * 68 + ks * 8 + t4 + 4];
                mma_tf32(sc[nt], a0, a1, a2, a3, b0, b1);
            }
        }

        // scale + mask
#pragma unroll
        for (int nt = 0; nt < 8; ++nt) {
            int c = j * 64 + nt * 8 + 2 * t4;
            int2 mk0 = __ldg((const int2*)(mrow0 + c));
            int2 mk1 = __ldg((const int2*)(mrow1 + c));
            sc[nt][0] = mk0.x ? sc[nt][0] * 0.125f : NEGINF;
            sc[nt][1] = mk0.y ? sc[nt][1] * 0.125f : NEGINF;
            sc[nt][2] = mk1.x ? sc[nt][2] * 0.125f : NEGINF;
            sc[nt][3] = mk1.y ? sc[nt][3] * 0.125f : NEGINF;
        }

        // online softmax (rows qrow0, qrow1), stats in registers
        float mx0 = -INFINITY, mx1 = -INFINITY;
#pragma unroll
        for (int nt = 0; nt < 8; ++nt) {
            mx0 = fmaxf(mx0, fmaxf(sc[nt][0], sc[nt][1]));
            mx1 = fmaxf(mx1, fmaxf(sc[nt][2], sc[nt][3]));
        }
        mx0 = fmaxf(mx0, __shfl_xor_sync(0xffffffffu, mx0, 1));
        mx0 = fmaxf(mx0, __shfl_xor_sync(0xffffffffu, mx0, 2));
        mx1 = fmaxf(mx1, __shfl_xor_sync(0xffffffffu, mx1, 1));
        mx1 = fmaxf(mx1, __shfl_xor_sync(0xffffffffu, mx1, 2));
        float mn0 = fmaxf(m0s, mx0), mn1 = fmaxf(m1s, mx1);
        float al0 = __expf(m0s - mn0), al1 = __expf(m1s - mn1);
        m0s = mn0; m1s = mn1;
        float rs0 = 0.0f, rs1 = 0.0f;
#pragma unroll
        for (int nt = 0; nt < 8; ++nt) {
            sc[nt][0] = __expf(sc[nt][0] - mn0);
            sc[nt][1] = __expf(sc[nt][1] - mn0);
            sc[nt][2] = __expf(sc[nt][2] - mn1);
            sc[nt][3] = __expf(sc[nt][3] - mn1);
            rs0 += sc[nt][0] + sc[nt][1];
            rs1 += sc[nt][2] + sc[nt][3];
        }
        rs0 += __shfl_xor_sync(0xffffffffu, rs0, 1);
        rs0 += __shfl_xor_sync(0xffffffffu, rs0, 2);
        rs1 += __shfl_xor_sync(0xffffffffu, rs1, 1);
        rs1 += __shfl_xor_sync(0xffffffffu, rs1, 2);
        l0 = al0 * l0 + rs0;
        l1 = al1 * l1 + rs1;
#pragma unroll
        for (int nt = 0; nt < 8; ++nt) {
            o[nt][0] *= al0; o[nt][1] *= al0;
            o[nt][2] *= al1; o[nt][3] *= al1;
        }

        // O += P @ V : relayout P C-frag -> A-frag via shfl, then mma
        const int s0l = (lane & ~3) | (t4 >> 1);
        const int s1l = s0l + 2;
        const bool odd = (t4 & 1);
#pragma unroll
        for (int kt = 0; kt < 8; ++kt) {
            float e00 = __shfl_sync(0xffffffffu, sc[kt][0], s0l);
            float e01 = __shfl_sync(0xffffffffu, sc[kt][1], s0l);
            float e10 = __shfl_sync(0xffffffffu, sc[kt][2], s0l);
            float e11 = __shfl_sync(0xffffffffu, sc[kt][3], s0l);
            float f00 = __shfl_sync(0xffffffffu, sc[kt][0], s1l);
            float f01 = __shfl_sync(0xffffffffu, sc[kt][1], s1l);
            float f10 = __shfl_sync(0xffffffffu, sc[kt][2], s1l);
            float f11 = __shfl_sync(0xffffffffu, sc[kt][3], s1l);
            unsigned a0 = f2tf(odd ? e01 : e00);
            unsigned a1 = f2tf(odd ? e11 : e10);
            unsigned a2 = f2tf(odd ? f01 : f00);
            unsigned a3 = f2tf(odd ? f11 : f10);
#pragma unroll
            for (int nt = 0; nt < 8; ++nt) {
                unsigned b0 = Vs[(kt * 8 + t4) * 72 + nt * 8 + g];
                unsigned b1 = Vs[(kt * 8 + t4 + 4) * 72 + nt * 8 + g];
                mma_tf32(o[nt], a0, a1, a2, a3, b0, b1);
            }
        }
        __syncthreads();
    }

    // epilogue: normalize, write ctx [B,S,D] at D col = h*64 + d
    const int bb = bh >> 4;
    const int h = bh & 15;
    float inv0 = 1.0f / l0, inv1 = 1.0f / l1;
#pragma unroll
    for (int nt = 0; nt < 8; ++nt) {
        int dcol = h * 64 + nt * 8 + 2 * t4;
        size_t r0 = ((size_t)bb * S_ + qrow0) * D_ + dcol;
        size_t r1 = ((size_t)bb * S_ + qrow1) * D_ + dcol;
        *(float2*)&g_C[r0] = make_float2(o[nt][0] * inv0, o[nt][1] * inv0);
        *(float2*)&g_C[r1] = make_float2(o[nt][2] * inv1, o[nt][3] * inv1);
    }
}

// ---------------------------------------------------------------------------
extern "C" void kernel_launch(void* const* d_in, const int* in_sizes, int n_in,
                              void* d_out, int out_size) {
    const float* x     = (const float*)d_in[0];
    const int*   mask  = (const int*)d_in[1];
    const float* w_qkv = (const float*)d_in[2];
    const float* b_qkv = (const float*)d_in[3];
    const float* w_o   = (const float*)d_in[4];
    const float* b_o   = (const float*)d_in[5];
    float* out = (float*)d_out;

    const int gemm_smem = (128 * 68 + 64 * 68) * (int)sizeof(unsigned);  // 52224
    const int attn_smem = (128 * 68 + 64 * 68 + 64 * 72) * (int)sizeof(unsigned);  // 70656

    cudaFuncSetAttribute(gemm_tc<0>, cudaFuncAttributeMaxDynamicSharedMemorySize, gemm_smem);
    cudaFuncSetAttribute(gemm_tc<1>, cudaFuncAttributeMaxDynamicSharedMemorySize, gemm_smem);
    cudaFuncSetAttribute(attn_tc, cudaFuncAttributeMaxDynamicSharedMemorySize, attn_smem);

    // 1) QKV projection
    gemm_tc<0><<<dim3(3072 / 64, 4096 / 128), 256, gemm_smem>>>(x, w_qkv, b_qkv, nullptr);

    // 2) flash attention
    attn_tc<<<dim3(S_ / 128, B_ * H_), 256, attn_smem>>>(mask);

    // 3) output projection
    gemm_tc<1><<<dim3(1024 / 64, 4096 / 128), 256, gemm_smem>>>(nullptr, w_o, b_o, out);
}

// round 3
// speedup vs baseline: 3.5598x; 1.1403x over previous
#include <cuda_runtime.h>
#include <math.h>

#define B_ 2
#define S_ 2048
#define D_ 1024
#define H_ 16
#define HD_ 64
#define NEGINF (-9000000000000000.0f)

// Scratch (device globals: allocation-free rule)
__device__ float g_Q[B_ * H_ * S_ * HD_];
__device__ float g_K[B_ * H_ * S_ * HD_];
__device__ float g_V[B_ * H_ * S_ * HD_];
__device__ float g_C[B_ * S_ * D_];
__device__ unsigned g_Mb[S_ * (S_ / 32)];   // bit-packed mask, 512 KB

__device__ __forceinline__ unsigned f2tf(float x) {
    unsigned r;
    asm("cvt.rna.tf32.f32 %0, %1;" : "=r"(r) : "f"(x));
    return r;
}

__device__ __forceinline__ void mma_tf32(float c[4], unsigned a0, unsigned a1,
                                         unsigned a2, unsigned a3,
                                         unsigned b0, unsigned b1) {
    asm volatile(
        "mma.sync.aligned.m16n8k8.row.col.f32.tf32.tf32.f32 "
        "{%0,%1,%2,%3}, {%4,%5,%6,%7}, {%8,%9}, {%0,%1,%2,%3};"
        : "+f"(c[0]), "+f"(c[1]), "+f"(c[2]), "+f"(c[3])
        : "r"(a0), "r"(a1), "r"(a2), "r"(a3), "r"(b0), "r"(b1));
}

// ---------------------------------------------------------------------------
// Pack mask[1,1,S,S] (int32) into bit matrix g_Mb[S][S/32].
// ---------------------------------------------------------------------------
__global__ __launch_bounds__(256) void maskpack(const int* __restrict__ mask) {
    int idx = blockIdx.x * 256 + threadIdx.x;   // word index, 131072 total
    int r = idx >> 6, wc = idx & 63;
    const int4* p = (const int4*)(mask + (size_t)r * S_ + wc * 32);
    unsigned bits = 0;
#pragma unroll
    for (int i = 0; i < 8; ++i) {
        int4 m = __ldg(p + i);
        bits |= (unsigned)(m.x != 0) << (4 * i)
              | (unsigned)(m.y != 0) << (4 * i + 1)
              | (unsigned)(m.z != 0) << (4 * i + 2)
              | (unsigned)(m.w != 0) << (4 * i + 3);
    }
    g_Mb[idx] = bits;
}

// ---------------------------------------------------------------------------
// Tensor-core GEMM: C[M,N] = A[M,1024] @ W[N,1024]^T + bias
// Block 128x128, BK=32, double-buffered smem, register prefetch, ONE barrier
// per k-iter. 8 warps (2x4), warp tile 64x32 (4 m16 x 4 n8).
// smem stride 36 -> conflict-free frag loads (bank = 4g+t4) and STS.
// MODE 0: A=x, N=3072, scatter into g_Q/g_K/g_V. MODE 1: A=g_C, N=1024.
// ---------------------------------------------------------------------------
template <int MODE>
__global__ __launch_bounds__(256, 2) void gemm_tc(const float* __restrict__ A,
                                                  const float* __restrict__ W,
                                                  const float* __restrict__ bias,
                                                  float* __restrict__ out) {
    extern __shared__ unsigned sh[];
    unsigned* As = sh;                  // [2][128][36]
    unsigned* Bs = sh + 2 * 128 * 36;   // [2][128][36]

    const int m0 = blockIdx.y * 128;
    const int n0 = blockIdx.x * 128;
    const int t = threadIdx.x;
    const int w = t >> 5;
    const int lane = t & 31;
    const int g = lane >> 2;
    const int t4 = lane & 3;
    const int wm = (w >> 2) * 64;
    const int wn = (w & 3) * 32;

    const int lrow = t >> 3;      // 0..31 base row step (idx>>3)
    const int lseg = t & 7;       // 0..7

    const float* Aptr = (MODE == 1 ? g_C : A);

    float4 ar[4], br[4];
    // prologue: load k-tile 0
#pragma unroll
    for (int i = 0; i < 4; ++i) {
        int row = lrow + i * 32;
        ar[i] = *(const float4*)(Aptr + (size_t)(m0 + row) * D_ + lseg * 4);
        br[i] = *(const float4*)(W + (size_t)(n0 + row) * D_ + lseg * 4);
    }
#pragma unroll
    for (int i = 0; i < 4; ++i) {
        int row = lrow + i * 32;
        unsigned* pa = &As[row * 36 + lseg * 4];
        pa[0] = f2tf(ar[i].x); pa[1] = f2tf(ar[i].y);
        pa[2] = f2tf(ar[i].z); pa[3] = f2tf(ar[i].w);
        unsigned* pb = &Bs[row * 36 + lseg * 4];
        pb[0] = f2tf(br[i].x); pb[1] = f2tf(br[i].y);
        pb[2] = f2tf(br[i].z); pb[3] = f2tf(br[i].w);
    }
    __syncthreads();

    float acc[4][4][4];
#pragma unroll
    for (int mt = 0; mt < 4; ++mt)
#pragma unroll
        for (int nt = 0; nt < 4; ++nt)
#pragma unroll
            for (int i = 0; i < 4; ++i) acc[mt][nt][i] = 0.0f;

    for (int k0 = 0; k0 < 32; ++k0) {
        const int kb = (k0 & 1) * 128 * 36;
        if (k0 < 31) {
            int kofs = (k0 + 1) * 32;
#pragma unroll
            for (int i = 0; i < 4; ++i) {
                int row = lrow + i * 32;
                ar[i] = *(const float4*)(Aptr + (size_t)(m0 + row) * D_ + kofs + lseg * 4);
                br[i] = *(const float4*)(W + (size_t)(n0 + row) * D_ + kofs + lseg * 4);
            }
        }
#pragma unroll
        for (int ks = 0; ks < 4; ++ks) {
            unsigned a[4][4];
#pragma unroll
            for (int mt = 0; mt < 4; ++mt) {
                const unsigned* q = &As[kb + (wm + mt * 16) * 36 + ks * 8];
                a[mt][0] = q[g * 36 + t4];
                a[mt][1] = q[(g + 8) * 36 + t4];
                a[mt][2] = q[g * 36 + t4 + 4];
                a[mt][3] = q[(g + 8) * 36 + t4 + 4];
            }
#pragma unroll
            for (int nt = 0; nt < 4; ++nt) {
                unsigned b0 = Bs[kb + (wn + nt * 8 + g) * 36 + ks * 8 + t4];
                unsigned b1 = Bs[kb + (wn + nt * 8 + g) * 36 + ks * 8 + t4 + 4];
#pragma unroll
                for (int mt = 0; mt < 4; ++mt)
                    mma_tf32(acc[mt][nt], a[mt][0], a[mt][1], a[mt][2], a[mt][3], b0, b1);
            }
        }
        if (k0 < 31) {
            const int nb = ((k0 + 1) & 1) * 128 * 36;
#pragma unroll
            for (int i = 0; i < 4; ++i) {
                int row = lrow + i * 32;
                unsigned* pa = &As[nb + row * 36 + lseg * 4];
                pa[0] = f2tf(ar[i].x); pa[1] = f2tf(ar[i].y);
                pa[2] = f2tf(ar[i].z); pa[3] = f2tf(ar[i].w);
                unsigned* pb = &Bs[nb + row * 36 + lseg * 4];
                pb[0] = f2tf(br[i].x); pb[1] = f2tf(br[i].y);
                pb[2] = f2tf(br[i].z); pb[3] = f2tf(br[i].w);
            }
        }
        __syncthreads();
    }

    // epilogue
#pragma unroll
    for (int mt = 0; mt < 4; ++mt) {
#pragma unroll
        for (int nt = 0; nt < 4; ++nt) {
            int ncol = n0 + wn + nt * 8 + 2 * t4;
            float bx = __ldg(&bias[ncol]);
            float by = __ldg(&bias[ncol + 1]);
#pragma unroll
            for (int rr = 0; rr < 2; ++rr) {
                int m = m0 + wm + mt * 16 + g + rr * 8;
                float vx = acc[mt][nt][rr * 2] + bx;
                float vy = acc[mt][nt][rr * 2 + 1] + by;
                if (MODE == 0) {
                    int bb = m >> 11, ss = m & 2047;
                    int h = ncol / 192;
                    int rem = ncol - h * 192;
                    int part = rem >> 6;
                    int d = rem & 63;
                    size_t dst = (((size_t)(bb * H_ + h)) * S_ + ss) * HD_ + d;
                    float* dstp = (part == 0 ? g_Q : (part == 1 ? g_K : g_V));
                    dstp[dst] = vx;
                    dstp[dst + 1] = vy;
                } else {
                    *(float2*)&out[(size_t)m * D_ + ncol] = make_float2(vx, vy);
                }
            }
        }
    }
}

// ---------------------------------------------------------------------------
// Flash attention, tf32 mma. grid=(S/128, B*H), 256 threads.
// Double-buffered K/V smem + register prefetch, ONE barrier per k-tile.
// Mask read from bit-packed g_Mb (8x less traffic). Warp owns 16 full q-rows
// -> softmax stats in registers. Qs/Ks stride 68, Vs stride 72 (conflict-free).
// ---------------------------------------------------------------------------
__global__ __launch_bounds__(256, 2) void attn_tc() {
    extern __shared__ unsigned sh[];
    unsigned* Qs = sh;                        // [128][68]
    unsigned* Ks = sh + 128 * 68;             // [2][64][68]
    unsigned* Vs = Ks + 2 * 64 * 68;          // [2][64][72]

    const int bh = blockIdx.y;
    const int q0 = blockIdx.x * 128;
    const int t = threadIdx.x;
    const int w = t >> 5;
    const int lane = t & 31;
    const int g = lane >> 2;
    const int t4 = lane & 3;

    const size_t base = (size_t)bh * (S_ * HD_);
    const float* Qg = g_Q + base;
    const float* Kg = g_K + base;
    const float* Vg = g_V + base;

    const int lrow = t >> 4;   // 0..15, K/V tile row step (+16 per i)
    const int lseg = t & 15;   // 0..15

    // stage Q tile
#pragma unroll
    for (int i = 0; i < 8; ++i) {
        int idx = t + i * 256;
        int row = idx >> 4, seg = idx & 15;
        float4 v = *(const float4*)(Qg + (size_t)(q0 + row) * HD_ + seg * 4);
        unsigned* p = &Qs[row * 68 + seg * 4];
        p[0] = f2tf(v.x); p[1] = f2tf(v.y); p[2] = f2tf(v.z); p[3] = f2tf(v.w);
    }

    // stage K/V tile 0 into buffer 0
    float4 kr[4], vr[4];
#pragma unroll
    for (int i = 0; i < 4; ++i) {
        int row = lrow + i * 16;
        kr[i] = *(const float4*)(Kg + (size_t)row * HD_ + lseg * 4);
        vr[i] = *(const float4*)(Vg + (size_t)row * HD_ + lseg * 4);
    }
#pragma unroll
    for (int i = 0; i < 4; ++i) {
        int row = lrow + i * 16;
        unsigned* p = &Ks[row * 68 + lseg * 4];
        p[0] = f2tf(kr[i].x); p[1] = f2tf(kr[i].y); p[2] = f2tf(kr[i].z); p[3] = f2tf(kr[i].w);
        unsigned* q = &Vs[row * 72 + lseg * 4];
        q[0] = f2tf(vr[i].x); q[1] = f2tf(vr[i].y); q[2] = f2tf(vr[i].z); q[3] = f2tf(vr[i].w);
    }

    const int qrow0 = q0 + w * 16 + g;
    const int qrow1 = qrow0 + 8;
    const unsigned* mbp0 = g_Mb + (size_t)qrow0 * 64;
    const unsigned* mbp1 = g_Mb + (size_t)qrow1 * 64;

    float o[8][4];
#pragma unroll
    for (int nt = 0; nt < 8; ++nt)
#pragma unroll
        for (int i = 0; i < 4; ++i) o[nt][i] = 0.0f;
    float m0s = -INFINITY, m1s = -INFINITY, l0 = 0.0f, l1 = 0.0f;

    __syncthreads();

    for (int j = 0; j < 32; ++j) {
        const int kbK = (j & 1) * 64 * 68;
        const int kbV = (j & 1) * 64 * 72;
        if (j < 31) {
            const float* Kn = Kg + (size_t)(j + 1) * 64 * HD_;
            const float* Vn = Vg + (size_t)(j + 1) * 64 * HD_;
#pragma unroll
            for (int i = 0; i < 4; ++i) {
                int row = lrow + i * 16;
                kr[i] = *(const float4*)(Kn + (size_t)row * HD_ + lseg * 4);
                vr[i] = *(const float4*)(Vn + (size_t)row * HD_ + lseg * 4);
            }
        }
        uint2 mb0 = *(const uint2*)(mbp0 + j * 2);
        uint2 mb1 = *(const uint2*)(mbp1 + j * 2);

        // S = Q @ K^T
        float sc[8][4];
#pragma unroll
        for (int nt = 0; nt < 8; ++nt)
#pragma unroll
            for (int i = 0; i < 4; ++i) sc[nt][i] = 0.0f;
#pragma unroll
        for (int ks = 0; ks < 8; ++ks) {
            const unsigned* qb = &Qs[(w * 16) * 68 + ks * 8];
            unsigned a0 = qb[g * 68 + t4];
            unsigned a1 = qb[(g + 8) * 68 + t4];
            unsigned a2 = qb[g * 68 + t4 + 4];
            unsigned a3 = qb[(g + 8) * 68 + t4 + 4];
#pragma unroll
            for (int nt = 0; nt < 8; ++nt) {
                unsigned b0 = Ks[kbK + (nt * 8 + g) * 68 + ks * 8 + t4];
                unsigned b1 = Ks[kbK + (nt * 8 + g) * 68 + ks * 8 + t4 + 4];
                mma_tf32(sc[nt], a0, a1, a2, a3, b0, b1);
            }
        }

        // scale + mask from bit matrix
#pragma unroll
        for (int nt = 0; nt < 8; ++nt) {
            unsigned w0 = (nt < 4) ? mb0.x : mb0.y;
            unsigned w1 = (nt < 4) ? mb1.x : mb1.y;
            int shv = (nt & 3) * 8 + 2 * t4;
            unsigned b0 = w0 >> shv;
            unsigned b1 = w1 >> shv;
            sc[nt][0] = (b0 & 1) ? sc[nt][0] * 0.125f : NEGINF;
            sc[nt][1] = (b0 & 2) ? sc[nt][1] * 0.125f : NEGINF;
            sc[nt][2] = (b1 & 1) ? sc[nt][2] * 0.125f : NEGINF;
            sc[nt][3] = (b1 & 2) ? sc[nt][3] * 0.125f : NEGINF;
        }

        // online softmax (register stats)
        float mx0 = -INFINITY, mx1 = -INFINITY;
#pragma unroll
        for (int nt = 0; nt < 8; ++nt) {
            mx0 = fmaxf(mx0, fmaxf(sc[nt][0], sc[nt][1]));
            mx1 = fmaxf(mx1, fmaxf(sc[nt][2], sc[nt][3]));
        }
        mx0 = fmaxf(mx0, __shfl_xor_sync(0xffffffffu, mx0, 1));
        mx0 = fmaxf(mx0, __shfl_xor_sync(0xffffffffu, mx0, 2));
        mx1 = fmaxf(mx1, __shfl_xor_sync(0xffffffffu, mx1, 1));
        mx1 = fmaxf(mx1, __shfl_xor_sync(0xffffffffu, mx1, 2));
        float mn0 = fmaxf(m0s, mx0), mn1 = fmaxf(m1s, mx1);
        float al0 = __expf(m0s - mn0), al1 = __expf(m1s - mn1);
        m0s = mn0; m1s = mn1;
        float rs0 = 0.0f, rs1 = 0.0f;
#pragma unroll
        for (int nt = 0; nt < 8; ++nt) {
            sc[nt][0] = __expf(sc[nt][0] - mn0);
            sc[nt][1] = __expf(sc[nt][1] - mn0);
            sc[nt][2] = __expf(sc[nt][2] - mn1);
            sc[nt][3] = __expf(sc[nt][3] - mn1);
            rs0 += sc[nt][0] + sc[nt][1];
            rs1 += sc[nt][2] + sc[nt][3];
        }
        rs0 += __shfl_xor_sync(0xffffffffu, rs0, 1);
        rs0 += __shfl_xor_sync(0xffffffffu, rs0, 2);
        rs1 += __shfl_xor_sync(0xffffffffu, rs1, 1);
        rs1 += __shfl_xor_sync(0xffffffffu, rs1, 2);
        l0 = al0 * l0 + rs0;
        l1 = al1 * l1 + rs1;
#pragma unroll
        for (int nt = 0; nt < 8; ++nt) {
            o[nt][0] *= al0; o[nt][1] *= al0;
            o[nt][2] *= al1; o[nt][3] *= al1;
        }

        // O += P @ V : relayout P C-frag -> A-frag via shfl
        const int s0l = (lane & ~3) | (t4 >> 1);
        const int s1l = s0l + 2;
        const bool odd = (t4 & 1);
#pragma unroll
        for (int kt = 0; kt < 8; ++kt) {
            float e00 = __shfl_sync(0xffffffffu, sc[kt][0], s0l);
            float e01 = __shfl_sync(0xffffffffu, sc[kt][1], s0l);
            float e10 = __shfl_sync(0xffffffffu, sc[kt][2], s0l);
            float e11 = __shfl_sync(0xffffffffu, sc[kt][3], s0l);
            float f00 = __shfl_sync(0xffffffffu, sc[kt][0], s1l);
            float f01 = __shfl_sync(0xffffffffu, sc[kt][1], s1l);
            float f10 = __shfl_sync(0xffffffffu, sc[kt][2], s1l);
            float f11 = __shfl_sync(0xffffffffu, sc[kt][3], s1l);
            unsigned a0 = f2tf(odd ? e01 : e00);
            unsigned a1 = f2tf(odd ? e11 : e10);
            unsigned a2 = f2tf(odd ? f01 : f00);
            unsigned a3 = f2tf(odd ? f11 : f10);
#pragma unroll
            for (int nt = 0; nt < 8; ++nt) {
                unsigned b0 = Vs[kbV + (kt * 8 + t4) * 72 + nt * 8 + g];
                unsigned b1 = Vs[kbV + (kt * 8 + t4 + 4) * 72 + nt * 8 + g];
                mma_tf32(o[nt], a0, a1, a2, a3, b0, b1);
            }
        }

        if (j < 31) {
            const int nbK = ((j + 1) & 1) * 64 * 68;
            const int nbV = ((j + 1) & 1) * 64 * 72;
#pragma unroll
            for (int i = 0; i < 4; ++i) {
                int row = lrow + i * 16;
                unsigned* p = &Ks[nbK + row * 68 + lseg * 4];
                p[0] = f2tf(kr[i].x); p[1] = f2tf(kr[i].y);
                p[2] = f2tf(kr[i].z); p[3] = f2tf(kr[i].w);
                unsigned* q = &Vs[nbV + row * 72 + lseg * 4];
                q[0] = f2tf(vr[i].x); q[1] = f2tf(vr[i].y);
                q[2] = f2tf(vr[i].z); q[3] = f2tf(vr[i].w);
            }
        }
        __syncthreads();
    }

    // epilogue: normalize, write ctx [B,S,D]
    const int bb = bh >> 4;
    const int h = bh & 15;
    float inv0 = 1.0f / l0, inv1 = 1.0f / l1;
#pragma unroll
    for (int nt = 0; nt < 8; ++nt) {
        int dcol = h * 64 + nt * 8 + 2 * t4;
        size_t r0 = ((size_t)bb * S_ + qrow0) * D_ + dcol;
        size_t r1 = ((size_t)bb * S_ + qrow1) * D_ + dcol;
        *(float2*)&g_C[r0] = make_float2(o[nt][0] * inv0, o[nt][1] * inv0);
        *(float2*)&g_C[r1] = make_float2(o[nt][2] * inv1, o[nt][3] * inv1);
    }
}

// ---------------------------------------------------------------------------
extern "C" void kernel_launch(void* const* d_in, const int* in_sizes, int n_in,
                              void* d_out, int out_size) {
    const float* x     = (const float*)d_in[0];
    const int*   mask  = (const int*)d_in[1];
    const float* w_qkv = (const float*)d_in[2];
    const float* b_qkv = (const float*)d_in[3];
    const float* w_o   = (const float*)d_in[4];
    const float* b_o   = (const float*)d_in[5];
    float* out = (float*)d_out;

    const int gemm_smem = 4 * 128 * 36 * (int)sizeof(unsigned);               // 73728
    const int attn_smem = (128 * 68 + 2 * 64 * 68 + 2 * 64 * 72) * (int)sizeof(unsigned); // 106496

    cudaFuncSetAttribute(gemm_tc<0>, cudaFuncAttributeMaxDynamicSharedMemorySize, gemm_smem);
    cudaFuncSetAttribute(gemm_tc<1>, cudaFuncAttributeMaxDynamicSharedMemorySize, gemm_smem);
    cudaFuncSetAttribute(attn_tc, cudaFuncAttributeMaxDynamicSharedMemorySize, attn_smem);

    // 0) pack mask bits
    maskpack<<<S_ * (S_ / 32) / 256, 256>>>(mask);

    // 1) QKV projection
    gemm_tc<0><<<dim3(3072 / 128, 4096 / 128), 256, gemm_smem>>>(x, w_qkv, b_qkv, nullptr);

    // 2) flash attention
    attn_tc<<<dim3(S_ / 128, B_ * H_), 256, attn_smem>>>();

    // 3) output projection
    gemm_tc<1><<<dim3(1024 / 128, 4096 / 128), 256, gemm_smem>>>(nullptr, w_o, b_o, out);
}